// round 3
// baseline (speedup 1.0000x reference)
#include <cuda_runtime.h>
#include <cstddef>

#define BB 32
#define TT 2048
#define DD 512
#define HH 512
#define G4 2048
#define NCTA 128
#define JC 4

// Scratch (device globals are the sanctioned allocation-free scratch)
__device__ float g_i2h[(size_t)BB * TT * G4];   // 512 MB, reused by both layers
__device__ float g_y0[(size_t)TT * BB * HH];    // layer-0 output, [t][b][j]
__device__ float g_hbuf[2][HH * BB];            // double-buffered h, [j][b]
__device__ unsigned g_bar;
__device__ volatile unsigned g_epoch;

__global__ void init_state_kernel() {
    int i = blockIdx.x * blockDim.x + threadIdx.x;
    if (i < HH * BB) g_hbuf[0][i] = 0.f;
    if (i == 0) { g_bar = 0u; g_epoch = 0u; }
}

__device__ __forceinline__ float sigf(float x) { return 1.f / (1.f + __expf(-x)); }
__device__ __forceinline__ float tanhf_(float x) {
    x = fminf(15.f, fmaxf(-15.f, x));
    float e = __expf(2.f * x);
    return (e - 1.f) / (e + 1.f);
}

// Packed f32x2 FMA — Blackwell FFMA2, only reachable via PTX.
__device__ __forceinline__ unsigned long long fma2(
    unsigned long long a, unsigned long long b, unsigned long long c)
{
    unsigned long long d;
    asm("fma.rn.f32x2 %0, %1, %2, %3;" : "=l"(d) : "l"(a), "l"(b), "l"(c));
    return d;
}

union U2 { unsigned long long u; float2 f; };

// C[M,2048] = A[M,512] @ W[2048,512]^T + bias ; M = 65536, tiles 128x128x16.
// A tile stored DUPLICATED in smem so FFMA2 row-broadcast operands load as pairs.
__global__ __launch_bounds__(256, 2) void gemm_kernel(
    const float* __restrict__ A, const float* __restrict__ W,
    const float* __restrict__ bias, float* __restrict__ C)
{
    __shared__ float As2[16][256];   // [k][2*row] duplicated
    __shared__ float Ws[16][128];    // [k][col]
    const int tid = threadIdx.x;
    const int tx = tid & 15, ty = tid >> 4;
    const int m0 = blockIdx.y * 128, n0 = blockIdx.x * 128;

    unsigned long long acc[8][4];
    #pragma unroll
    for (int i = 0; i < 8; i++)
        #pragma unroll
        for (int j = 0; j < 4; j++) acc[i][j] = 0ull;

    const int lr = tid >> 1;          // 0..127 (tile row)
    const int lc = (tid & 1) * 2;     // float4-column base {0,2}

    for (int k0 = 0; k0 < DD; k0 += 16) {
        __syncthreads();
        #pragma unroll
        for (int l = 0; l < 2; l++) {
            int cc = lc + l;  // 0..3
            float4 va = *reinterpret_cast<const float4*>(&A[(size_t)(m0 + lr) * DD + k0 + cc * 4]);
            // duplicated stores as 8-byte pairs
            *reinterpret_cast<float2*>(&As2[cc*4+0][2*lr]) = make_float2(va.x, va.x);
            *reinterpret_cast<float2*>(&As2[cc*4+1][2*lr]) = make_float2(va.y, va.y);
            *reinterpret_cast<float2*>(&As2[cc*4+2][2*lr]) = make_float2(va.z, va.z);
            *reinterpret_cast<float2*>(&As2[cc*4+3][2*lr]) = make_float2(va.w, va.w);
            float4 vw = *reinterpret_cast<const float4*>(&W[(size_t)(n0 + lr) * DD + k0 + cc * 4]);
            Ws[cc*4+0][lr] = vw.x; Ws[cc*4+1][lr] = vw.y;
            Ws[cc*4+2][lr] = vw.z; Ws[cc*4+3][lr] = vw.w;
        }
        __syncthreads();
        #pragma unroll
        for (int k = 0; k < 16; k++) {
            ulonglong2 a01 = *reinterpret_cast<const ulonglong2*>(&As2[k][ty * 16]);
            ulonglong2 a23 = *reinterpret_cast<const ulonglong2*>(&As2[k][ty * 16 + 4]);
            ulonglong2 a45 = *reinterpret_cast<const ulonglong2*>(&As2[k][ty * 16 + 8]);
            ulonglong2 a67 = *reinterpret_cast<const ulonglong2*>(&As2[k][ty * 16 + 12]);
            ulonglong2 b03 = *reinterpret_cast<const ulonglong2*>(&Ws[k][tx * 8]);
            ulonglong2 b47 = *reinterpret_cast<const ulonglong2*>(&Ws[k][tx * 8 + 4]);
            unsigned long long av[8] = {a01.x, a01.y, a23.x, a23.y,
                                        a45.x, a45.y, a67.x, a67.y};
            unsigned long long bp[4] = {b03.x, b03.y, b47.x, b47.y};
            #pragma unroll
            for (int i = 0; i < 8; i++)
                #pragma unroll
                for (int j = 0; j < 4; j++)
                    acc[i][j] = fma2(av[i], bp[j], acc[i][j]);
        }
    }
    float4 bs0 = *reinterpret_cast<const float4*>(&bias[n0 + tx*8]);
    float4 bs1 = *reinterpret_cast<const float4*>(&bias[n0 + tx*8 + 4]);
    #pragma unroll
    for (int i = 0; i < 8; i++) {
        size_t row = (size_t)(m0 + ty*8 + i) * G4 + n0 + tx*8;
        U2 p0; p0.u = acc[i][0];
        U2 p1; p1.u = acc[i][1];
        U2 p2; p2.u = acc[i][2];
        U2 p3; p3.u = acc[i][3];
        float4 o0 = make_float4(p0.f.x+bs0.x, p0.f.y+bs0.y, p1.f.x+bs0.z, p1.f.y+bs0.w);
        float4 o1 = make_float4(p2.f.x+bs1.x, p2.f.y+bs1.y, p3.f.x+bs1.z, p3.f.y+bs1.w);
        *reinterpret_cast<float4*>(&C[row])     = o0;
        *reinterpret_cast<float4*>(&C[row + 4]) = o1;
    }
}

// Persistent recurrence: 128 CTAs, CTA owns 4 hidden units (16 gate rows).
// ws2: [k][2*r_loc] DUPLICATED gate-row weights (resident all steps, f32x2 feed).
// hs:  [k][b] h broadcast, staged per-warp (each warp only its 64-k slice).
__global__ __launch_bounds__(256, 1) void lstm_recur_kernel(
    const float* __restrict__ Wh, const float* __restrict__ bh,
    const float* __restrict__ i2h, float* __restrict__ yout,
    float* __restrict__ hc_out, int layer)
{
    extern __shared__ float sm[];
    float* ws2 = sm;                  // 512*32 (duplicated)
    float* hs  = ws2 + 512 * 32;      // 512*32
    float* red = hs + 512 * 32;       // 512*8
    float* bhs = red + 512 * 8;       // 16
    float* cs  = bhs + 16;            // 128

    const int tid = threadIdx.x;
    const int j0 = blockIdx.x * JC;

    {   // stage weights transposed + duplicated: ws2[k][2*rl{,+1}], rl = g*4 + jj
        int rl = tid >> 4;
        int k0 = (tid & 15) * 32;
        int g = rl >> 2, jj = rl & 3;
        const float* wrow = Wh + (size_t)(g * HH + j0 + jj) * HH;
        #pragma unroll 8
        for (int kk = 0; kk < 32; kk++) {
            float v = wrow[k0 + kk];
            *reinterpret_cast<float2*>(&ws2[(k0 + kk) * 32 + 2 * rl]) = make_float2(v, v);
        }
        if (tid < 16) bhs[tid] = bh[(tid >> 2) * HH + j0 + (tid & 3)];
        if (tid < 128) cs[tid] = 0.f;
    }
    __syncthreads();

    const int ks = tid >> 5;           // K slice (64 k each), one per warp
    const int lane = tid & 31;
    const int rt = (tid >> 3) & 3;     // row quad
    const int bt = tid & 7;            // batch quad
    const ulonglong2* wsu2 = reinterpret_cast<const ulonglong2*>(ws2);
    const ulonglong2* hsu2 = reinterpret_cast<const ulonglong2*>(hs);

    for (int t = 0; t < TT; t++) {
        // i2h prefetch: depends only on t, cover DRAM latency under compute
        float pre0 = 0.f, pre1 = 0.f, pre2 = 0.f, pre3 = 0.f;
        const int b_  = tid & 31;
        const int jj_ = tid >> 5;
        if (tid < 128) {
            const size_t mrow = (layer == 0) ? ((size_t)b_ * TT + t)
                                             : ((size_t)t * BB + b_);
            const float* irow = i2h + mrow * G4 + j0 + jj_;
            pre0 = __ldcg(irow);
            pre1 = __ldcg(irow + HH);
            pre2 = __ldcg(irow + 2 * HH);
            pre3 = __ldcg(irow + 3 * HH);
        }

        // per-warp h staging: warp ks needs only k in [64ks, 64ks+64)
        {
            const float4* hsrc = reinterpret_cast<const float4*>(g_hbuf[t & 1]);
            float4* hdst = reinterpret_cast<float4*>(hs);
            #pragma unroll
            for (int i = 0; i < 16; i++)
                hdst[ks * 512 + lane + i * 32] = __ldcg(&hsrc[ks * 512 + lane + i * 32]);
            __syncwarp();
        }

        unsigned long long acc[4][2];
        #pragma unroll
        for (int ri = 0; ri < 4; ri++) {
            acc[ri][0] = 0ull; acc[ri][1] = 0ull;
        }

        const int kend = ks * 64 + 64;
        #pragma unroll 8
        for (int k = ks * 64; k < kend; k++) {
            ulonglong2 w01 = wsu2[k * 8 + rt * 2];      // dup rows 4rt, 4rt+1
            ulonglong2 w23 = wsu2[k * 8 + rt * 2 + 1];  // dup rows 4rt+2, 4rt+3
            ulonglong2 hp  = hsu2[k * 8 + bt];          // batch pairs 4bt..4bt+3
            acc[0][0] = fma2(w01.x, hp.x, acc[0][0]);
            acc[0][1] = fma2(w01.x, hp.y, acc[0][1]);
            acc[1][0] = fma2(w01.y, hp.x, acc[1][0]);
            acc[1][1] = fma2(w01.y, hp.y, acc[1][1]);
            acc[2][0] = fma2(w23.x, hp.x, acc[2][0]);
            acc[2][1] = fma2(w23.x, hp.y, acc[2][1]);
            acc[3][0] = fma2(w23.y, hp.x, acc[3][0]);
            acc[3][1] = fma2(w23.y, hp.y, acc[3][1]);
        }
        #pragma unroll
        for (int ri = 0; ri < 4; ri++)
            #pragma unroll
            for (int p = 0; p < 2; p++) {
                U2 v; v.u = acc[ri][p];
                red[((rt * 4 + ri) * 32 + bt * 4 + 2 * p) * 8 + ks]     = v.f.x;
                red[((rt * 4 + ri) * 32 + bt * 4 + 2 * p + 1) * 8 + ks] = v.f.y;
            }
        __syncthreads();

        if (tid < 128) {   // one thread per (b, jj)
            const int b  = b_;
            const int jj = jj_;
            const int j  = j0 + jj;
            float pre[4] = {pre0, pre1, pre2, pre3};
            float gate[4];
            #pragma unroll
            for (int g = 0; g < 4; g++) {
                const int rr = g * 4 + jj;
                const float4* rp = reinterpret_cast<const float4*>(&red[(rr * 32 + b) * 8]);
                float4 s0 = rp[0], s1 = rp[1];
                gate[g] = ((s0.x + s0.y) + (s0.z + s0.w))
                        + ((s1.x + s1.y) + (s1.z + s1.w))
                        + pre[g] + bhs[rr];
            }
            float ig = sigf(gate[0]);
            float fg = sigf(gate[1]);
            float cg = tanhf_(gate[2]);
            float og = sigf(gate[3]);
            float c_new = fmaf(fg, cs[tid], ig * cg);
            float h_new = og * tanhf_(c_new);
            cs[tid] = c_new;
            g_hbuf[(t + 1) & 1][j * BB + b] = h_new;
            if (layer == 0)
                yout[((size_t)t * BB + b) * HH + j] = h_new;   // [t][b][j]
            else
                yout[((size_t)b * TT + t) * HH + j] = h_new;   // y1 [b][t][j]
            if (t == TT - 1) {
                hc_out[(size_t)layer * BB * HH + b * HH + j]       = h_new;
                hc_out[(size_t)(2 + layer) * BB * HH + b * HH + j] = c_new;
            }
        }

        if (t < TT - 1) {
            __threadfence();
            __syncthreads();
            if (tid == 0) {
                unsigned target = (unsigned)(t + 1) * NCTA;
                unsigned a = atomicAdd(&g_bar, 1u) + 1u;
                if (a == target) g_epoch = (unsigned)(t + 1);
                else while (g_epoch < (unsigned)(t + 1)) { }
            }
            __syncthreads();
        }
    }
}

extern "C" void kernel_launch(void* const* d_in, const int* in_sizes, int n_in,
                              void* d_out, int out_size)
{
    (void)in_sizes; (void)n_in; (void)out_size;
    const float* x   = (const float*)d_in[0];
    const float* Wi0 = (const float*)d_in[1];
    const float* bi0 = (const float*)d_in[2];
    const float* Wh0 = (const float*)d_in[3];
    const float* bh0 = (const float*)d_in[4];
    const float* Wi1 = (const float*)d_in[5];
    const float* bi1 = (const float*)d_in[6];
    const float* Wh1 = (const float*)d_in[7];
    const float* bh1 = (const float*)d_in[8];
    float* out = (float*)d_out;

    float *i2h_p, *y0_p;
    cudaGetSymbolAddress((void**)&i2h_p, g_i2h);
    cudaGetSymbolAddress((void**)&y0_p,  g_y0);

    const int SMEM = (512*32 + 512*32 + 512*8 + 16 + 128) * (int)sizeof(float);
    cudaFuncSetAttribute(lstm_recur_kernel,
                         cudaFuncAttributeMaxDynamicSharedMemorySize, SMEM);

    dim3 ggrid(G4 / 128, (BB * TT) / 128);
    float* hc = out + (size_t)BB * TT * HH;

    // Layer 0
    gemm_kernel<<<ggrid, 256>>>(x, Wi0, bi0, i2h_p);
    init_state_kernel<<<64, 256>>>();
    lstm_recur_kernel<<<NCTA, 256, SMEM>>>(Wh0, bh0, i2h_p, y0_p, hc, 0);
    // Layer 1
    gemm_kernel<<<ggrid, 256>>>(y0_p, Wi1, bi1, i2h_p);
    init_state_kernel<<<64, 256>>>();
    lstm_recur_kernel<<<NCTA, 256, SMEM>>>(Wh1, bh1, i2h_p, out, hc, 1);
}

// round 4
// speedup vs baseline: 1.1684x; 1.1684x over previous
#include <cuda_runtime.h>
#include <cstddef>

#define BB 32
#define TT 2048
#define DD 512
#define HH 512
#define G4 2048
#define NCTA 128
#define JC 4

// Scratch (device globals are the sanctioned allocation-free scratch)
__device__ float g_i2h[(size_t)BB * TT * G4];   // 512 MB, reused by both layers
__device__ float g_y0[(size_t)TT * BB * HH];    // layer-0 output, [t][b][j]
__device__ float g_hbuf[2][HH * BB];            // double-buffered h, [j][b]
__device__ unsigned g_bar;
__device__ unsigned g_epoch;

__global__ void init_state_kernel() {
    int i = blockIdx.x * blockDim.x + threadIdx.x;
    if (i < HH * BB) g_hbuf[0][i] = 0.f;
    if (i == 0) { g_bar = 0u; g_epoch = 0u; }
}

__device__ __forceinline__ float sigf(float x) { return 1.f / (1.f + __expf(-x)); }
__device__ __forceinline__ float tanhf_(float x) {
    x = fminf(15.f, fmaxf(-15.f, x));
    float e = __expf(2.f * x);
    return (e - 1.f) / (e + 1.f);
}

// C[M,2048] = A[M,512] @ W[2048,512]^T + bias ; M = 65536, tiles 128x128x16.
// Double-buffered smem: LDG for k-tile i+1 issues before compute of tile i.
__global__ __launch_bounds__(256, 2) void gemm_kernel(
    const float* __restrict__ A, const float* __restrict__ W,
    const float* __restrict__ bias, float* __restrict__ C)
{
    __shared__ float As[2][16][128];
    __shared__ float Ws[2][16][128];
    const int tid = threadIdx.x;
    const int tx = tid & 15, ty = tid >> 4;
    const int m0 = blockIdx.y * 128, n0 = blockIdx.x * 128;

    float acc[8][8];
    #pragma unroll
    for (int i = 0; i < 8; i++)
        #pragma unroll
        for (int j = 0; j < 8; j++) acc[i][j] = 0.f;

    const int lr = tid >> 1;          // 0..127 (tile row)
    const int lc = (tid & 1) * 2;     // float4-column base {0,2}
    const float* Arow = A + (size_t)(m0 + lr) * DD;
    const float* Wrow = W + (size_t)(n0 + lr) * DD;

    float4 ra0, ra1, rw0, rw1;
    // prologue: stage k0 = 0
    ra0 = *reinterpret_cast<const float4*>(&Arow[lc * 4]);
    ra1 = *reinterpret_cast<const float4*>(&Arow[(lc + 1) * 4]);
    rw0 = *reinterpret_cast<const float4*>(&Wrow[lc * 4]);
    rw1 = *reinterpret_cast<const float4*>(&Wrow[(lc + 1) * 4]);
    {
        int c0 = lc, c1 = lc + 1;
        As[0][c0*4+0][lr] = ra0.x; As[0][c0*4+1][lr] = ra0.y;
        As[0][c0*4+2][lr] = ra0.z; As[0][c0*4+3][lr] = ra0.w;
        As[0][c1*4+0][lr] = ra1.x; As[0][c1*4+1][lr] = ra1.y;
        As[0][c1*4+2][lr] = ra1.z; As[0][c1*4+3][lr] = ra1.w;
        Ws[0][c0*4+0][lr] = rw0.x; Ws[0][c0*4+1][lr] = rw0.y;
        Ws[0][c0*4+2][lr] = rw0.z; Ws[0][c0*4+3][lr] = rw0.w;
        Ws[0][c1*4+0][lr] = rw1.x; Ws[0][c1*4+1][lr] = rw1.y;
        Ws[0][c1*4+2][lr] = rw1.z; Ws[0][c1*4+3][lr] = rw1.w;
    }
    __syncthreads();

    int p = 0;
    for (int k0 = 0; k0 < DD; k0 += 16) {
        const bool more = (k0 + 16 < DD);
        if (more) {   // issue next-tile LDG early; latency hides under compute
            ra0 = *reinterpret_cast<const float4*>(&Arow[k0 + 16 + lc * 4]);
            ra1 = *reinterpret_cast<const float4*>(&Arow[k0 + 16 + (lc + 1) * 4]);
            rw0 = *reinterpret_cast<const float4*>(&Wrow[k0 + 16 + lc * 4]);
            rw1 = *reinterpret_cast<const float4*>(&Wrow[k0 + 16 + (lc + 1) * 4]);
        }
        #pragma unroll
        for (int k = 0; k < 16; k++) {
            float4 a0 = *reinterpret_cast<const float4*>(&As[p][k][ty * 8]);
            float4 a1 = *reinterpret_cast<const float4*>(&As[p][k][ty * 8 + 4]);
            float4 b0 = *reinterpret_cast<const float4*>(&Ws[p][k][tx * 8]);
            float4 b1 = *reinterpret_cast<const float4*>(&Ws[p][k][tx * 8 + 4]);
            float av[8] = {a0.x,a0.y,a0.z,a0.w,a1.x,a1.y,a1.z,a1.w};
            float bv[8] = {b0.x,b0.y,b0.z,b0.w,b1.x,b1.y,b1.z,b1.w};
            #pragma unroll
            for (int i = 0; i < 8; i++)
                #pragma unroll
                for (int j = 0; j < 8; j++)
                    acc[i][j] = fmaf(av[i], bv[j], acc[i][j]);
        }
        if (more) {
            int q = 1 - p;
            int c0 = lc, c1 = lc + 1;
            As[q][c0*4+0][lr] = ra0.x; As[q][c0*4+1][lr] = ra0.y;
            As[q][c0*4+2][lr] = ra0.z; As[q][c0*4+3][lr] = ra0.w;
            As[q][c1*4+0][lr] = ra1.x; As[q][c1*4+1][lr] = ra1.y;
            As[q][c1*4+2][lr] = ra1.z; As[q][c1*4+3][lr] = ra1.w;
            Ws[q][c0*4+0][lr] = rw0.x; Ws[q][c0*4+1][lr] = rw0.y;
            Ws[q][c0*4+2][lr] = rw0.z; Ws[q][c0*4+3][lr] = rw0.w;
            Ws[q][c1*4+0][lr] = rw1.x; Ws[q][c1*4+1][lr] = rw1.y;
            Ws[q][c1*4+2][lr] = rw1.z; Ws[q][c1*4+3][lr] = rw1.w;
            __syncthreads();
            p = q;
        }
    }

    float4 bs0 = *reinterpret_cast<const float4*>(&bias[n0 + tx*8]);
    float4 bs1 = *reinterpret_cast<const float4*>(&bias[n0 + tx*8 + 4]);
    #pragma unroll
    for (int i = 0; i < 8; i++) {
        size_t row = (size_t)(m0 + ty*8 + i) * G4 + n0 + tx*8;
        float4 o0 = make_float4(acc[i][0]+bs0.x, acc[i][1]+bs0.y, acc[i][2]+bs0.z, acc[i][3]+bs0.w);
        float4 o1 = make_float4(acc[i][4]+bs1.x, acc[i][5]+bs1.y, acc[i][6]+bs1.z, acc[i][7]+bs1.w);
        *reinterpret_cast<float4*>(&C[row])     = o0;
        *reinterpret_cast<float4*>(&C[row + 4]) = o1;
    }
}

// Persistent recurrence: 128 CTAs, CTA owns 4 hidden units (16 gate rows).
// ws: [k][16] gate-row weights resident in smem all 2048 steps.
// h is read straight from global (L2-hot, __ldcg) into register chunks — no
// smem staging. Global barrier = release-atomic + acquire-poll (no membar.gpu).
__global__ __launch_bounds__(256, 1) void lstm_recur_kernel(
    const float* __restrict__ Wh, const float* __restrict__ bh,
    const float* __restrict__ i2h, float* __restrict__ yout,
    float* __restrict__ hc_out, int layer)
{
    extern __shared__ float sm[];
    float* ws  = sm;                 // 512*16
    float* red = ws + 512 * 16;      // 512*8
    float* bhs = red + 512 * 8;      // 16
    float* cs  = bhs + 16;           // 128

    const int tid = threadIdx.x;
    const int j0 = blockIdx.x * JC;

    {   // stage weights transposed: ws[k][rl], rl = g*4 + jj
        int rl = tid >> 4;
        int k0 = (tid & 15) * 32;
        int g = rl >> 2, jj = rl & 3;
        const float* wrow = Wh + (size_t)(g * HH + j0 + jj) * HH;
        #pragma unroll 8
        for (int kk = 0; kk < 32; kk++)
            ws[(k0 + kk) * 16 + rl] = wrow[k0 + kk];
        if (tid < 16) bhs[tid] = bh[(tid >> 2) * HH + j0 + (tid & 3)];
        if (tid < 128) cs[tid] = 0.f;
    }
    __syncthreads();

    const int ks = tid >> 5;           // K slice (64 k each), one per warp
    const int rt = (tid >> 3) & 3;     // row quad
    const int bt = tid & 7;            // batch quad
    const int b_  = tid & 31;
    const int jj_ = tid >> 5;
    const float4* ws4 = reinterpret_cast<const float4*>(ws);

    for (int t = 0; t < TT; t++) {
        // i2h prefetch: depends only on t, hides DRAM latency under the FMA loop
        float pre0 = 0.f, pre1 = 0.f, pre2 = 0.f, pre3 = 0.f;
        if (tid < 128) {
            const size_t mrow = (layer == 0) ? ((size_t)b_ * TT + t)
                                             : ((size_t)t * BB + b_);
            const float* irow = i2h + mrow * G4 + j0 + jj_;
            pre0 = __ldcg(irow);
            pre1 = __ldcg(irow + HH);
            pre2 = __ldcg(irow + 2 * HH);
            pre3 = __ldcg(irow + 3 * HH);
        }

        const float4* hsrc4 = reinterpret_cast<const float4*>(g_hbuf[t & 1]);
        const int kb = ks * 64;

        float acc[4][4];
        #pragma unroll
        for (int ri = 0; ri < 4; ri++)
            #pragma unroll
            for (int bi = 0; bi < 4; bi++) acc[ri][bi] = 0.f;

        #pragma unroll
        for (int c = 0; c < 8; c++) {          // 8 chunks x 8 k
            float4 hp[8];
            #pragma unroll
            for (int i = 0; i < 8; i++)
                hp[i] = __ldcg(&hsrc4[(size_t)(kb + c * 8 + i) * 8 + bt]);
            #pragma unroll
            for (int i = 0; i < 8; i++) {
                const int k = kb + c * 8 + i;
                float4 wv = ws4[k * 4 + rt];
                acc[0][0] = fmaf(wv.x, hp[i].x, acc[0][0]);
                acc[0][1] = fmaf(wv.x, hp[i].y, acc[0][1]);
                acc[0][2] = fmaf(wv.x, hp[i].z, acc[0][2]);
                acc[0][3] = fmaf(wv.x, hp[i].w, acc[0][3]);
                acc[1][0] = fmaf(wv.y, hp[i].x, acc[1][0]);
                acc[1][1] = fmaf(wv.y, hp[i].y, acc[1][1]);
                acc[1][2] = fmaf(wv.y, hp[i].z, acc[1][2]);
                acc[1][3] = fmaf(wv.y, hp[i].w, acc[1][3]);
                acc[2][0] = fmaf(wv.z, hp[i].x, acc[2][0]);
                acc[2][1] = fmaf(wv.z, hp[i].y, acc[2][1]);
                acc[2][2] = fmaf(wv.z, hp[i].z, acc[2][2]);
                acc[2][3] = fmaf(wv.z, hp[i].w, acc[2][3]);
                acc[3][0] = fmaf(wv.w, hp[i].x, acc[3][0]);
                acc[3][1] = fmaf(wv.w, hp[i].y, acc[3][1]);
                acc[3][2] = fmaf(wv.w, hp[i].z, acc[3][2]);
                acc[3][3] = fmaf(wv.w, hp[i].w, acc[3][3]);
            }
        }
        #pragma unroll
        for (int ri = 0; ri < 4; ri++)
            #pragma unroll
            for (int bi = 0; bi < 4; bi++)
                red[((rt * 4 + ri) * 32 + bt * 4 + bi) * 8 + ks] = acc[ri][bi];
        __syncthreads();

        if (tid < 128) {   // one thread per (b, jj)
            const int b  = b_;
            const int jj = jj_;
            const int j  = j0 + jj;
            float pre[4] = {pre0, pre1, pre2, pre3};
            float gate[4];
            #pragma unroll
            for (int g = 0; g < 4; g++) {
                const int rr = g * 4 + jj;
                const float4* rp = reinterpret_cast<const float4*>(&red[(rr * 32 + b) * 8]);
                float4 s0 = rp[0], s1 = rp[1];
                gate[g] = ((s0.x + s0.y) + (s0.z + s0.w))
                        + ((s1.x + s1.y) + (s1.z + s1.w))
                        + pre[g] + bhs[rr];
            }
            float ig = sigf(gate[0]);
            float fg = sigf(gate[1]);
            float cg = tanhf_(gate[2]);
            float og = sigf(gate[3]);
            float c_new = fmaf(fg, cs[tid], ig * cg);
            float h_new = og * tanhf_(c_new);
            cs[tid] = c_new;
            g_hbuf[(t + 1) & 1][j * BB + b] = h_new;
            if (layer == 0)
                yout[((size_t)t * BB + b) * HH + j] = h_new;   // [t][b][j]
            else
                yout[((size_t)b * TT + t) * HH + j] = h_new;   // y1 [b][t][j]
            if (t == TT - 1) {
                hc_out[(size_t)layer * BB * HH + b * HH + j]       = h_new;
                hc_out[(size_t)(2 + layer) * BB * HH + b * HH + j] = c_new;
            }
        }

        if (t < TT - 1) {
            // bar.sync orders all threads' h-stores before tid0's release-atomic;
            // consumer side: acquire-poll then bar.sync orders subsequent __ldcg.
            __syncthreads();
            if (tid == 0) {
                const unsigned target = (unsigned)(t + 1) * NCTA;
                unsigned prev;
                asm volatile("atom.release.gpu.add.u32 %0, [%1], %2;"
                             : "=r"(prev) : "l"(&g_bar), "r"(1u) : "memory");
                if (prev + 1u == target) {
                    asm volatile("st.release.gpu.u32 [%0], %1;"
                                 :: "l"(&g_epoch), "r"((unsigned)(t + 1)) : "memory");
                } else {
                    unsigned e;
                    do {
                        asm volatile("ld.acquire.gpu.u32 %0, [%1];"
                                     : "=r"(e) : "l"(&g_epoch) : "memory");
                    } while (e < (unsigned)(t + 1));
                }
            }
            __syncthreads();
        }
    }
}

extern "C" void kernel_launch(void* const* d_in, const int* in_sizes, int n_in,
                              void* d_out, int out_size)
{
    (void)in_sizes; (void)n_in; (void)out_size;
    const float* x   = (const float*)d_in[0];
    const float* Wi0 = (const float*)d_in[1];
    const float* bi0 = (const float*)d_in[2];
    const float* Wh0 = (const float*)d_in[3];
    const float* bh0 = (const float*)d_in[4];
    const float* Wi1 = (const float*)d_in[5];
    const float* bi1 = (const float*)d_in[6];
    const float* Wh1 = (const float*)d_in[7];
    const float* bh1 = (const float*)d_in[8];
    float* out = (float*)d_out;

    float *i2h_p, *y0_p;
    cudaGetSymbolAddress((void**)&i2h_p, g_i2h);
    cudaGetSymbolAddress((void**)&y0_p,  g_y0);

    const int SMEM = (512*16 + 512*8 + 16 + 128) * (int)sizeof(float);
    cudaFuncSetAttribute(lstm_recur_kernel,
                         cudaFuncAttributeMaxDynamicSharedMemorySize, SMEM);

    dim3 ggrid(G4 / 128, (BB * TT) / 128);
    float* hc = out + (size_t)BB * TT * HH;

    // Layer 0
    gemm_kernel<<<ggrid, 256>>>(x, Wi0, bi0, i2h_p);
    init_state_kernel<<<64, 256>>>();
    lstm_recur_kernel<<<NCTA, 256, SMEM>>>(Wh0, bh0, i2h_p, y0_p, hc, 0);
    // Layer 1
    gemm_kernel<<<ggrid, 256>>>(y0_p, Wi1, bi1, i2h_p);
    init_state_kernel<<<64, 256>>>();
    lstm_recur_kernel<<<NCTA, 256, SMEM>>>(Wh1, bh1, i2h_p, out, hc, 1);
}